// round 14
// baseline (speedup 1.0000x reference)
#include <cuda_runtime.h>
#include <cuda_fp16.h>
#include <stdint.h>

#define D_    64
#define NROW  16384
#define KCB   8192
#define BM    16
#define BN    128
#define NT    128
#define KT    64
#define CAPS  96
#define PI8   80     // int8 row pitch
#define PH    144    // fp16 A row pitch (16*9, 16B-aligned, conflict-free)
#define EPS_H 5.2e-4f

__device__ float    g_xsq[NROW];
__device__ float    g_wsq[KCB];
__device__ float    g_xl1[NROW];
__device__ float    g_xamax[NROW];
__device__ int      g_wamax_bits;
__device__ int      g_wl1max_bits;
__device__ int      g_wsqmax_bits;
__device__ uint32_t g_xq8[NROW * 16];   // int8x4 packed
__device__ uint32_t g_wq8[KCB * 16];
__device__ uint32_t g_xh[NROW * 32];    // half2 packed
__device__ uint32_t g_wh[KCB * 32];
__device__ unsigned long long g_loss_acc;
__device__ int      g_done;

// ---------------------------------------------------------------------------
__device__ __forceinline__ uint32_t smem_u32(const void* p) {
    uint32_t a;
    asm("{ .reg .u64 t; cvta.to.shared.u64 t, %1; cvt.u32.u64 %0, t; }" : "=r"(a) : "l"(p));
    return a;
}
__device__ __forceinline__ void cp16(uint32_t dst, const void* src) {
    asm volatile("cp.async.cg.shared.global [%0], [%1], 16;" :: "r"(dst), "l"(src));
}
__device__ __forceinline__ void cp_commit() { asm volatile("cp.async.commit_group;"); }
__device__ __forceinline__ void cp_wait1()  { asm volatile("cp.async.wait_group 1;"); }
__device__ __forceinline__ void cp_wait0()  { asm volatile("cp.async.wait_group 0;"); }

__device__ __forceinline__ int dp4a_(uint32_t a, uint32_t b, int c) {
    int d;
    asm("dp4a.s32.s32 %0, %1, %2, %3;" : "=r"(d) : "r"(a), "r"(b), "r"(c));
    return d;
}
__device__ __forceinline__ __half2 h2fma(uint32_t a, uint32_t b, __half2 c) {
    return __hfma2(*reinterpret_cast<__half2*>(&a), *reinterpret_cast<__half2*>(&b), c);
}
__device__ __forceinline__ uint32_t pack4(float a, float b, float c, float d, float inv) {
    int q0 = __float2int_rn(a * inv) & 0xff;
    int q1 = __float2int_rn(b * inv) & 0xff;
    int q2 = __float2int_rn(c * inv) & 0xff;
    int q3 = __float2int_rn(d * inv) & 0xff;
    return (uint32_t)(q0 | (q1 << 8) | (q2 << 16) | (q3 << 24));
}

// ---------------------------------------------------------------------------
// prepA: warp-per-row stats, int8 x quantize, fp16 x/w convert, global maxes
// ---------------------------------------------------------------------------
__global__ __launch_bounds__(256) void prepA_kernel(const float* __restrict__ x,
                                                    const float* __restrict__ w) {
    if (blockIdx.x == 0 && threadIdx.x == 0) { g_loss_acc = 0ULL; g_done = 0; }
    int gw = (blockIdx.x * 256 + threadIdx.x) >> 5;
    int lane = threadIdx.x & 31;
    if (gw >= NROW + KCB) return;
    const bool isX = (gw < NROW);
    const float* src = isX ? x : w;
    int row = isX ? gw : gw - NROW;

    float2 v = ((const float2*)(src + (size_t)row * D_))[lane];
    __half2 h = __floats2half2_rn(v.x, v.y);
    float s  = v.x * v.x + v.y * v.y;
    float l1 = fabsf(v.x) + fabsf(v.y);
    float am = fmaxf(fabsf(v.x), fabsf(v.y));
#pragma unroll
    for (int o = 16; o > 0; o >>= 1) {
        s  += __shfl_xor_sync(0xffffffffu, s, o);
        l1 += __shfl_xor_sync(0xffffffffu, l1, o);
        am  = fmaxf(am, __shfl_xor_sync(0xffffffffu, am, o));
    }
    if (isX) {
        g_xh[row * 32 + lane] = *reinterpret_cast<uint32_t*>(&h);
        float amc = fmaxf(am, 1e-30f);
        float inv = 127.f / amc;
        int q0 = __float2int_rn(v.x * inv) & 0xff;
        int q1 = __float2int_rn(v.y * inv) & 0xff;
        uint32_t v16 = (uint32_t)(q0 | (q1 << 8));
        uint32_t hi = __shfl_down_sync(0xffffffffu, v16, 1);
        if (!(lane & 1)) g_xq8[row * 16 + (lane >> 1)] = v16 | (hi << 16);
        if (lane == 0) { g_xsq[row] = s; g_xl1[row] = l1; g_xamax[row] = amc; }
    } else {
        g_wh[row * 32 + lane] = *reinterpret_cast<uint32_t*>(&h);
        if (lane == 0) {
            g_wsq[row] = s;
            atomicMax(&g_wamax_bits,  __float_as_int(am));
            atomicMax(&g_wl1max_bits, __float_as_int(l1));
            atomicMax(&g_wsqmax_bits, __float_as_int(s));
        }
    }
}

// ---------------------------------------------------------------------------
// prepW2: int8 quantize w with global scale (needs wamax from prepA)
// ---------------------------------------------------------------------------
__global__ __launch_bounds__(256) void prepW2_kernel(const float* __restrict__ w) {
    int r = blockIdx.x * 256 + threadIdx.x;
    if (r >= KCB) return;
    float wam = fmaxf(__int_as_float(g_wamax_bits), 1e-30f);
    float inv = 127.f / wam;
    const float4* wr = (const float4*)(w + (size_t)r * D_);
#pragma unroll
    for (int q = 0; q < 16; q++) {
        float4 v = wr[q];
        g_wq8[r * 16 + q] = pack4(v.x, v.y, v.z, v.w, inv);
    }
}

// ---------------------------------------------------------------------------
// vq_fused: dual-pipe filter (warps specialized: dp4a cols 0-63, HFMA2 64-127)
//           + in-CTA exact fp32 rescore + gather + fixed-point loss
// out: [0]=loss, [1..N*D]=quantized, [1+N*D..]=indices (float)
// ---------------------------------------------------------------------------
__global__ __launch_bounds__(NT, 6) void vq_fused(const float* __restrict__ x,
                                                  const float* __restrict__ w,
                                                  float* __restrict__ out) {
    __shared__ uint8_t xsA[BM * PI8];          // 1280
    __shared__ uint8_t xhA[BM * PH];           // 2304
    __shared__ uint8_t w8s[2][64 * PI8];       // 2 x 5120
    __shared__ uint8_t whs[2][64 * 128];       // 2 x 8192 (16B-chunk swizzled)
    __shared__ float   wsqs[2][BN];            // 2 x 512
    __shared__ int     s_gmin[BM];
    __shared__ int     s_cnt[BM];
    __shared__ int     s_cand[BM][CAPS];       // 6144
    __shared__ int     s_idx[BM];
    __shared__ float   s_lred[NT / 32];

    const uint32_t sbA8 = smem_u32(xsA);
    const uint32_t sbAH = smem_u32(xhA);
    const uint32_t sbW8 = smem_u32(w8s);
    const uint32_t sbWH = smem_u32(whs);
    const uint32_t sbQ  = smem_u32(wsqs);

    const int t = threadIdx.x;
    const int lane = t & 31, wid = t >> 5;
    const int rg = lane >> 3;        // row group 0..3 (rows rg + 4r)
    const int cg = lane & 7;         // col group 0..7 (cols cg + 8c)
    const int rowBase = blockIdx.x * BM;
    const int type = (wid + ((blockIdx.x >> 2) & 1)) & 1;  // 0=int8, 1=fp16
    const int wid2 = wid >> 1;       // sub-strip 0/1 within type
    const int colb = wid2 * 32;      // strip-local col base
    const int gcolb = (type ? 64 : 0) + colb;   // tile-local col base

    if (t < BM) { s_gmin[t] = 0x7F800000; s_cnt[t] = 0; }

    // A tiles
    if (t < 64) {
        int r = t >> 2, q = t & 3;
        cp16(sbA8 + r * PI8 + q * 16, g_xq8 + (size_t)(rowBase + r) * 16 + q * 4);
    }
    {
        int r = t >> 3, q = t & 7;
        cp16(sbAH + r * PH + q * 16, g_xh + (size_t)(rowBase + r) * 32 + q * 4);
    }
    auto issue = [&](int tt, int b) {
#pragma unroll
        for (int i = 0; i < 2; i++) {          // int8 strip: 256 chunks
            int idx = t + i * NT;
            int r = idx >> 2, q = idx & 3;
            cp16(sbW8 + b * (64 * PI8) + r * PI8 + q * 16,
                 g_wq8 + ((size_t)tt * BN + r) * 16 + q * 4);
        }
#pragma unroll
        for (int i = 0; i < 4; i++) {          // fp16 strip: 512 chunks, swizzled
            int idx = t + i * NT;
            int lc = idx >> 3, q = idx & 7;
            cp16(sbWH + b * 8192 + lc * 128 + ((q * 16) ^ ((lc & 7) * 16)),
                 g_wh + ((size_t)tt * BN + 64 + lc) * 32 + q * 4);
        }
        if (t < 32) cp16(sbQ + b * (BN * 4) + t * 16, g_wsq + tt * BN + t * 4);
    };

    issue(0, 0);
    cp_commit();

    // ---- per-lane row constants (rows rg + 4r) ----
    const float wam  = fmaxf(__int_as_float(g_wamax_bits), 1e-30f);
    const float sw   = wam * (1.f / 127.f);
    const float l1wm = __int_as_float(g_wl1max_bits);
    const float wsqm = fmaxf(__int_as_float(g_wsqmax_bits), 0.f);

    float xqs[4], c2s[4], m2B[4];
#pragma unroll
    for (int r = 0; r < 4; r++) {
        int row = rowBase + rg + 4 * r;
        float xam = g_xamax[row];
        float l1x = g_xl1[row];
        float sx  = xam * (1.f / 127.f);
        float de8 = 0.5f * sw * l1x + 0.5f * sx * l1wm + 16.f * sx * sw;
        float deh = EPS_H * (32.f * sqrtf(g_xsq[row] * wsqm) + l1x * wam + xam * l1wm);
        float demax = fmaxf(de8, deh);
        xqs[r] = g_xsq[row];
        c2s[r] = -2.f * sx * sw;
        m2B[r] = 2.f * ((type ? deh : de8) + demax);
        (void)0;
    }

    int acc8[4][4];
    __half2 acch[4][4];
    const __half2 hz = __float2half2_rn(0.f);

    for (int tt = 0; tt < KT; tt++) {
        const int buf = tt & 1;
        if (tt + 1 < KT) { issue(tt + 1, buf ^ 1); cp_commit(); cp_wait1(); }
        else             { cp_wait0(); }
        __syncthreads();

        float wq[4], lmin[4] = {3.4e38f, 3.4e38f, 3.4e38f, 3.4e38f};
#pragma unroll
        for (int c = 0; c < 4; c++) wq[c] = wsqs[buf][gcolb + cg + 8 * c];

        if (type == 0) {
            const uint8_t* wt = w8s[buf];
#pragma unroll
            for (int r = 0; r < 4; r++)
#pragma unroll
                for (int c = 0; c < 4; c++) acc8[r][c] = 0;
#pragma unroll
            for (int kq2 = 0; kq2 < 8; kq2++) {
                uint2 a2[4], b2[4];
#pragma unroll
                for (int r = 0; r < 4; r++)
                    a2[r] = *(const uint2*)(xsA + (rg + 4 * r) * PI8 + kq2 * 8);
#pragma unroll
                for (int c = 0; c < 4; c++)
                    b2[c] = *(const uint2*)(wt + (colb + cg + 8 * c) * PI8 + kq2 * 8);
#pragma unroll
                for (int r = 0; r < 4; r++)
#pragma unroll
                    for (int c = 0; c < 4; c++) {
                        acc8[r][c] = dp4a_(a2[r].x, b2[c].x, acc8[r][c]);
                        acc8[r][c] = dp4a_(a2[r].y, b2[c].y, acc8[r][c]);
                    }
            }
#pragma unroll
            for (int c = 0; c < 4; c++)
#pragma unroll
                for (int r = 0; r < 4; r++) {
                    float d = fmaf(c2s[r], (float)acc8[r][c], xqs[r] + wq[c]);
                    lmin[r] = fminf(lmin[r], d);
                }
        } else {
            const uint8_t* wt = whs[buf];
#pragma unroll
            for (int r = 0; r < 4; r++)
#pragma unroll
                for (int c = 0; c < 4; c++) acch[r][c] = hz;
#pragma unroll
            for (int s = 0; s < 16; s++) {
                uint2 ah[4], bh[4];
#pragma unroll
                for (int r = 0; r < 4; r++)
                    ah[r] = *(const uint2*)(xhA + (rg + 4 * r) * PH + s * 8);
#pragma unroll
                for (int c = 0; c < 4; c++) {
                    int lc = colb + cg + 8 * c;
                    bh[c] = *(const uint2*)(wt + lc * 128 +
                              (((s >> 1) * 16) ^ ((lc & 7) * 16)) + (s & 1) * 8);
                }
#pragma unroll
                for (int r = 0; r < 4; r++)
#pragma unroll
                    for (int c = 0; c < 4; c++) {
                        acch[r][c] = h2fma(ah[r].x, bh[c].x, acch[r][c]);
                        acch[r][c] = h2fma(ah[r].y, bh[c].y, acch[r][c]);
                    }
            }
#pragma unroll
            for (int c = 0; c < 4; c++)
#pragma unroll
                for (int r = 0; r < 4; r++) {
                    float2 f2 = __half22float2(acch[r][c]);
                    float d = fmaf(-2.f, f2.x + f2.y, xqs[r] + wq[c]);
                    lmin[r] = fminf(lmin[r], d);
                }
        }

        // shared row-min update (positive floats: int compare valid)
#pragma unroll
        for (int r = 0; r < 4; r++) {
            float v = lmin[r];
            v = fminf(v, __shfl_xor_sync(0xffffffffu, v, 1));
            v = fminf(v, __shfl_xor_sync(0xffffffffu, v, 2));
            v = fminf(v, __shfl_xor_sync(0xffffffffu, v, 4));
            if (cg == 0) atomicMin(&s_gmin[rg + 4 * r], __float_as_int(v));
        }
        __syncthreads();

        // append pass (recompute d; threshold from shared min)
        float thr[4];
#pragma unroll
        for (int r = 0; r < 4; r++) thr[r] = __int_as_float(s_gmin[rg + 4 * r]) + m2B[r];

#pragma unroll
        for (int c = 0; c < 4; c++) {
            int gcol = tt * BN + gcolb + cg + 8 * c;
#pragma unroll
            for (int r = 0; r < 4; r++) {
                float d;
                if (type == 0) {
                    d = fmaf(c2s[r], (float)acc8[r][c], xqs[r] + wq[c]);
                } else {
                    float2 f2 = __half22float2(acch[r][c]);
                    d = fmaf(-2.f, f2.x + f2.y, xqs[r] + wq[c]);
                }
                if (d <= thr[r]) {
                    int lrow = rg + 4 * r;
                    int p = atomicAdd(&s_cnt[lrow], 1);
                    if (p < CAPS) s_cand[lrow][p] = gcol;
                }
            }
        }
        __syncthreads();
    }

    // ---- in-CTA exact fp32 rescore (warp wid: rows 4*wid..4*wid+3) ----
#pragma unroll 1
    for (int rr = 0; rr < 4; rr++) {
        int lrow = wid * 4 + rr;
        int row = rowBase + lrow;
        int cnt = s_cnt[lrow];
        if (cnt > CAPS) cnt = CAPS;
        float2 xv = ((const float2*)(x + (size_t)row * D_))[lane];
        float xq = g_xsq[row];
        float bd = 3.4e38f;
        int   bc = 0x7fffffff;
        for (int i = 0; i < cnt; i++) {
            int c0 = s_cand[lrow][i];
            float2 w0 = ((const float2*)(w + (size_t)c0 * D_))[lane];
            float p0 = xv.x * w0.x + xv.y * w0.y;
#pragma unroll
            for (int o = 16; o > 0; o >>= 1) p0 += __shfl_xor_sync(0xffffffffu, p0, o);
            float d0 = xq + g_wsq[c0] - 2.f * p0;
            if (d0 < bd || (d0 == bd && c0 < bc)) { bd = d0; bc = c0; }
        }
        if (lane == 0) {
            s_idx[lrow] = bc;
            out[1 + (size_t)NROW * D_ + row] = (float)bc;
        }
    }
    __syncthreads();

    // ---- gather + deterministic fixed-point loss ----
    float lsum = 0.f;
#pragma unroll
    for (int i = 0; i < 8; i++) {
        int idx = t + i * NT;
        int r = idx >> 6, dc = idx & 63;
        float q = w[(size_t)s_idx[r] * D_ + dc];
        out[1 + (size_t)(rowBase + r) * D_ + dc] = q;
        float df = q - x[(size_t)(rowBase + r) * D_ + dc];
        lsum += df * df;
    }
#pragma unroll
    for (int o = 16; o > 0; o >>= 1) lsum += __shfl_down_sync(0xffffffffu, lsum, o);
    if (lane == 0) s_lred[wid] = lsum;
    __syncthreads();
    if (t == 0) {
        float s = 0.f;
#pragma unroll
        for (int wI = 0; wI < NT / 32; wI++) s += s_lred[wI];
        unsigned long long part = (unsigned long long)((double)s * 1048576.0);
        atomicAdd(&g_loss_acc, part);
        __threadfence();
        int done = atomicAdd(&g_done, 1);
        if (done == (int)gridDim.x - 1) {
            unsigned long long tot = *((volatile unsigned long long*)&g_loss_acc);
            out[0] = 1.25f * (float)((double)tot / 1048576.0) / (float)(NROW * D_);
        }
    }
}

// ---------------------------------------------------------------------------
extern "C" void kernel_launch(void* const* d_in, const int* in_sizes, int n_in,
                              void* d_out, int out_size) {
    const float* x = (const float*)d_in[0];
    const float* w = (const float*)d_in[1];
    float* out = (float*)d_out;

    prepA_kernel<<<(NROW + KCB) / 8, 256>>>(x, w);
    prepW2_kernel<<<KCB / 256, 256>>>(w);
    vq_fused<<<NROW / BM, NT>>>(x, w, out);
}

// round 15
// speedup vs baseline: 1.8456x; 1.8456x over previous
#include <cuda_runtime.h>
#include <stdint.h>

#define D_    64
#define NROW  16384
#define KCB   8192
#define BM    16
#define BN    128
#define NT    128
#define KT    (KCB / BN)     // 64
#define CAPS  128            // per-row smem candidate cap
#define PI8   80             // int8 row pitch in smem (64 data + 16 pad)

__device__ float    g_xsq[NROW];
__device__ float    g_wsq[KCB];
__device__ float    g_xl1[NROW];
__device__ float    g_xamax[NROW];
__device__ int      g_wamax_bits;
__device__ int      g_wl1max_bits;
__device__ uint32_t g_xq8[NROW * 16];   // packed int8x4
__device__ uint32_t g_wq8[KCB * 16];
__device__ unsigned long long g_loss_acc;
__device__ int      g_done;

// ---------------------------------------------------------------------------
__device__ __forceinline__ uint32_t smem_u32(const void* p) {
    uint32_t a;
    asm("{ .reg .u64 t; cvta.to.shared.u64 t, %1; cvt.u32.u64 %0, t; }" : "=r"(a) : "l"(p));
    return a;
}
__device__ __forceinline__ void cp16(uint32_t dst, const void* src) {
    asm volatile("cp.async.cg.shared.global [%0], [%1], 16;" :: "r"(dst), "l"(src));
}
__device__ __forceinline__ void cp_commit() { asm volatile("cp.async.commit_group;"); }
__device__ __forceinline__ void cp_wait1()  { asm volatile("cp.async.wait_group 1;"); }
__device__ __forceinline__ void cp_wait0()  { asm volatile("cp.async.wait_group 0;"); }

__device__ __forceinline__ int dp4a_(uint32_t a, uint32_t b, int c) {
    int d;
    asm("dp4a.s32.s32 %0, %1, %2, %3;" : "=r"(d) : "r"(a), "r"(b), "r"(c));
    return d;
}
__device__ __forceinline__ uint32_t pack4(float a, float b, float c, float d, float inv) {
    int q0 = __float2int_rn(a * inv) & 0xff;
    int q1 = __float2int_rn(b * inv) & 0xff;
    int q2 = __float2int_rn(c * inv) & 0xff;
    int q3 = __float2int_rn(d * inv) & 0xff;
    return (uint32_t)(q0 | (q1 << 8) | (q2 << 16) | (q3 << 24));
}

// ---------------------------------------------------------------------------
// prepA: warp-per-row. x rows: stats + int8 quantize. w rows: stats + maxes.
// Also resets the loss accumulator (graph-replay safe).
// ---------------------------------------------------------------------------
__global__ __launch_bounds__(256) void prepA_kernel(const float* __restrict__ x,
                                                    const float* __restrict__ w) {
    if (blockIdx.x == 0 && threadIdx.x == 0) { g_loss_acc = 0ULL; g_done = 0; }
    int gw = (blockIdx.x * 256 + threadIdx.x) >> 5;
    int lane = threadIdx.x & 31;
    if (gw >= NROW + KCB) return;
    const bool isX = (gw < NROW);
    const float* src = isX ? x : w;
    int row = isX ? gw : gw - NROW;

    float2 v = ((const float2*)(src + (size_t)row * D_))[lane];
    float s  = v.x * v.x + v.y * v.y;
    float l1 = fabsf(v.x) + fabsf(v.y);
    float am = fmaxf(fabsf(v.x), fabsf(v.y));
#pragma unroll
    for (int o = 16; o > 0; o >>= 1) {
        s  += __shfl_xor_sync(0xffffffffu, s, o);
        l1 += __shfl_xor_sync(0xffffffffu, l1, o);
        am  = fmaxf(am, __shfl_xor_sync(0xffffffffu, am, o));
    }
    if (isX) {
        float amc = fmaxf(am, 1e-30f);
        float inv = 127.f / amc;
        int q0 = __float2int_rn(v.x * inv) & 0xff;
        int q1 = __float2int_rn(v.y * inv) & 0xff;
        uint32_t v16 = (uint32_t)(q0 | (q1 << 8));
        uint32_t hi = __shfl_down_sync(0xffffffffu, v16, 1);
        if (!(lane & 1)) g_xq8[row * 16 + (lane >> 1)] = v16 | (hi << 16);
        if (lane == 0) {
            g_xsq[row] = s; g_xl1[row] = l1; g_xamax[row] = amc;
        }
    } else if (lane == 0) {
        g_wsq[row] = s;
        atomicMax(&g_wamax_bits,  __float_as_int(am));
        atomicMax(&g_wl1max_bits, __float_as_int(l1));
    }
}

// ---------------------------------------------------------------------------
// prepW2: quantize w to int8 with global scale
// ---------------------------------------------------------------------------
__global__ __launch_bounds__(256) void prepW2_kernel(const float* __restrict__ w) {
    int r = blockIdx.x * 256 + threadIdx.x;
    if (r >= KCB) return;
    float wam = fmaxf(__int_as_float(g_wamax_bits), 1e-30f);
    float inv = 127.f / wam;
    const float4* wr = (const float4*)(w + (size_t)r * D_);
#pragma unroll
    for (int q = 0; q < 16; q++) {
        float4 v = wr[q];
        g_wq8[r * 16 + q] = pack4(v.x, v.y, v.z, v.w, inv);
    }
}

// ---------------------------------------------------------------------------
// vq_fused: dp4a filter (smem candidates) + exact fp32 rescore + gather/loss
// 16x128 tiles, 128 threads, TM=2 x TN=8; grid=1024 for SM load balance
// out: [0]=loss, [1..N*D]=quantized, [1+N*D..]=indices (float)
// ---------------------------------------------------------------------------
__global__ __launch_bounds__(NT, 7) void vq_fused(const float* __restrict__ x,
                                                  const float* __restrict__ w,
                                                  float* __restrict__ out) {
    __shared__ uint8_t xsA[BM * PI8];            // 1280 B
    __shared__ uint8_t wsm[2][BN * PI8];         // 2 x 10240 B
    __shared__ float   wsqs[2][BN];              // 2 x 512 B
    __shared__ int     s_cnt[BM];
    __shared__ int     s_cand[BM][CAPS];         // 8192 B
    __shared__ int     s_idx[BM];
    __shared__ float   s_lred[NT / 32];

    const uint32_t sbA = smem_u32(xsA);
    const uint32_t sbW = smem_u32(wsm);
    const uint32_t sbQ = smem_u32(wsqs);

    const int t = threadIdx.x;
    const int tx = t & 15, ty = t >> 4;
    const int lane = t & 31, wid = t >> 5;
    const int rowBase = blockIdx.x * BM;

    if (t < BM) s_cnt[t] = 0;

    // A tile: 16 rows x 64B = 64 x 16B
    if (t < 64) {
        int r = t >> 2, q = t & 3;
        cp16(sbA + r * PI8 + q * 16, g_xq8 + (size_t)(rowBase + r) * 16 + q * 4);
    }
    auto issue = [&](int tt, int b) {
#pragma unroll
        for (int i = 0; i < 4; i++) {
            int idx = t + i * NT;                // 512 x 16B
            int r = idx >> 2, q = idx & 3;
            cp16(sbW + b * (BN * PI8) + r * PI8 + q * 16,
                 g_wq8 + ((size_t)tt * BN + r) * 16 + q * 4);
        }
        if (t < 32) cp16(sbQ + b * (BN * 4) + t * 16, g_wsq + tt * BN + t * 4);
    };

    issue(0, 0);
    cp_commit();

    // per-thread row state; margin = 4*doterr (E = 2*doterr on distances)
    const float wam = fmaxf(__int_as_float(g_wamax_bits), 1e-30f);
    const float sw  = wam * (1.f / 127.f);
    const float l1w = __int_as_float(g_wl1max_bits);

    float xqs[2], gmin[2], m2B[2], c2s[2];
#pragma unroll
    for (int r = 0; r < 2; r++) {
        int row = rowBase + ty + 8 * r;
        float xam = g_xamax[row];
        float sx  = xam * (1.f / 127.f);
        float doterr = 0.5f * sw * g_xl1[row] + 0.5f * sx * l1w + 16.f * sx * sw;
        xqs[r]  = g_xsq[row];
        m2B[r]  = 4.f * doterr;
        c2s[r]  = -2.f * sx * sw;
        gmin[r] = 3.4e38f;
    }

    for (int tt = 0; tt < KT; tt++) {
        const int buf = tt & 1;
        if (tt + 1 < KT) { issue(tt + 1, buf ^ 1); cp_commit(); cp_wait1(); }
        else             { cp_wait0(); }
        __syncthreads();

        const uint8_t* wt = wsm[buf];
        int acc[2][8];
#pragma unroll
        for (int r = 0; r < 2; r++)
#pragma unroll
            for (int c = 0; c < 8; c++) acc[r][c] = 0;

#pragma unroll
        for (int kq2 = 0; kq2 < 8; kq2++) {      // 8 bytes of k per step
            uint2 a2[2], b2[8];
#pragma unroll
            for (int r = 0; r < 2; r++)
                a2[r] = *(const uint2*)(xsA + (ty + 8 * r) * PI8 + kq2 * 8);
#pragma unroll
            for (int c = 0; c < 8; c++)
                b2[c] = *(const uint2*)(wt + (tx + 16 * c) * PI8 + kq2 * 8);
#pragma unroll
            for (int r = 0; r < 2; r++)
#pragma unroll
                for (int c = 0; c < 8; c++) {
                    acc[r][c] = dp4a_(a2[r].x, b2[c].x, acc[r][c]);
                    acc[r][c] = dp4a_(a2[r].y, b2[c].y, acc[r][c]);
                }
        }

        // ---- epilogue: compute all distances first ----
        const float* wqS = wsqs[buf];
        float dbuf[2][8];
#pragma unroll
        for (int c = 0; c < 8; c++) {
            float wq = wqS[tx + 16 * c];
#pragma unroll
            for (int r = 0; r < 2; r++) {
                float d = fmaf(c2s[r], (float)acc[r][c], xqs[r] + wq);
                dbuf[r][c] = d;
                gmin[r] = fminf(gmin[r], d);
            }
        }
        // tighten across the 16 lanes of this row (this tile included)
#pragma unroll
        for (int r = 0; r < 2; r++) {
            float v = gmin[r];
            v = fminf(v, __shfl_xor_sync(0xffffffffu, v, 1));
            v = fminf(v, __shfl_xor_sync(0xffffffffu, v, 2));
            v = fminf(v, __shfl_xor_sync(0xffffffffu, v, 4));
            v = fminf(v, __shfl_xor_sync(0xffffffffu, v, 8));
            gmin[r] = v;
        }
        // append with post-tile threshold (superset: final gmin <= current)
#pragma unroll
        for (int c = 0; c < 8; c++) {
            int gcol = tt * BN + tx + 16 * c;
#pragma unroll
            for (int r = 0; r < 2; r++) {
                if (dbuf[r][c] <= gmin[r] + m2B[r]) {
                    int lrow = ty + 8 * r;
                    int p = atomicAdd(&s_cnt[lrow], 1);
                    if (p < CAPS) s_cand[lrow][p] = gcol;
                }
            }
        }
        __syncthreads();
    }

    // ---- in-CTA exact fp32 rescore: warp wid handles rows 4*wid..4*wid+3 ----
#pragma unroll 1
    for (int rr = 0; rr < 4; rr++) {
        int lrow = wid * 4 + rr;
        int row = rowBase + lrow;
        int cnt = s_cnt[lrow];
        if (cnt > CAPS) cnt = CAPS;
        float2 xv = ((const float2*)(x + (size_t)row * D_))[lane];
        float xq = g_xsq[row];
        float bd = 3.4e38f;
        int   bc = 0x7fffffff;
        for (int i = 0; i < cnt; i++) {
            int c0 = s_cand[lrow][i];
            float2 w0 = ((const float2*)(w + (size_t)c0 * D_))[lane];
            float p0 = xv.x * w0.x + xv.y * w0.y;
#pragma unroll
            for (int o = 16; o > 0; o >>= 1) p0 += __shfl_xor_sync(0xffffffffu, p0, o);
            float d0 = xq + g_wsq[c0] - 2.f * p0;
            if (d0 < bd || (d0 == bd && c0 < bc)) { bd = d0; bc = c0; }
        }
        if (lane == 0) {
            s_idx[lrow] = bc;
            out[1 + (size_t)NROW * D_ + row] = (float)bc;
        }
    }
    __syncthreads();

    // ---- quantized gather + deterministic fixed-point loss ----
    float lsum = 0.f;
#pragma unroll
    for (int i = 0; i < 8; i++) {
        int idx = t + i * NT;                 // 1024 elements
        int r = idx >> 6, dc = idx & 63;
        float q = w[(size_t)s_idx[r] * D_ + dc];
        out[1 + (size_t)(rowBase + r) * D_ + dc] = q;
        float xf = x[(size_t)(rowBase + r) * D_ + dc];
        float df = q - xf;
        lsum += df * df;
    }
#pragma unroll
    for (int o = 16; o > 0; o >>= 1) lsum += __shfl_down_sync(0xffffffffu, lsum, o);
    if (lane == 0) s_lred[wid] = lsum;
    __syncthreads();
    if (t == 0) {
        float s = 0.f;
#pragma unroll
        for (int wI = 0; wI < NT / 32; wI++) s += s_lred[wI];
        // 2^20 fixed-point: integer adds commute -> deterministic across replays
        unsigned long long part = (unsigned long long)((double)s * 1048576.0);
        atomicAdd(&g_loss_acc, part);
        __threadfence();
        int done = atomicAdd(&g_done, 1);
        if (done == (int)gridDim.x - 1) {
            unsigned long long tot = *((volatile unsigned long long*)&g_loss_acc);
            out[0] = 1.25f * (float)((double)tot / 1048576.0) / (float)(NROW * D_);
        }
    }
}

// ---------------------------------------------------------------------------
extern "C" void kernel_launch(void* const* d_in, const int* in_sizes, int n_in,
                              void* d_out, int out_size) {
    const float* x = (const float*)d_in[0];
    const float* w = (const float*)d_in[1];
    float* out = (float*)d_out;

    prepA_kernel<<<(NROW + KCB) / 8, 256>>>(x, w);
    prepW2_kernel<<<KCB / 256, 256>>>(w);
    vq_fused<<<NROW / BM, NT>>>(x, w, out);
}